// round 16
// baseline (speedup 1.0000x reference)
#include <cuda_runtime.h>
#include <cuda_fp16.h>
#include <cstdint>

#define S_LEN 256
#define BATCH 64
#define HID   1024
#define G4    4096
#define RGRID 128

// ---------------- device scratch (no runtime allocation allowed) ------------
__device__ float    g_xz[(size_t)S_LEN * G4 * BATCH];  // 256 MB, layout [s][n][b]
__device__ __half   g_xh[(size_t)S_LEN * BATCH * HID]; // x in fp16 (33.5 MB)
__device__ __half   g_wh[(size_t)G4 * HID];            // Wx fp16, row n = gate*1024+j (8 MB)
__device__ unsigned g_h16[2][HID*BATCH/2];             // h ping-pong, fp16 frag-packed
__device__ unsigned g_bar;                             // monotonic grid barrier

// ---------------- helpers ----------------------------------------------------
__device__ __forceinline__ float tanh_ap(float x){
  float y; asm("tanh.approx.f32 %0, %1;" : "=f"(y) : "f"(x)); return y;
}
__device__ __forceinline__ void mma16h(float* d, const unsigned* a, unsigned b0, unsigned b1){
  asm volatile("mma.sync.aligned.m16n8k16.row.col.f32.f16.f16.f32 "
      "{%0,%1,%2,%3},{%4,%5,%6,%7},{%8,%9},{%0,%1,%2,%3};"
      : "+f"(d[0]),"+f"(d[1]),"+f"(d[2]),"+f"(d[3])
      : "r"(a[0]),"r"(a[1]),"r"(a[2]),"r"(a[3]),"r"(b0),"r"(b1));
}
__device__ __forceinline__ unsigned ld_acq(const unsigned* p){
  unsigned v; asm volatile("ld.acquire.gpu.global.u32 %0, [%1];" : "=r"(v) : "l"(p)); return v;
}
__device__ __forceinline__ uint4 ldcg4(const uint4* p){
  uint4 v;
  asm volatile("ld.global.cg.v4.u32 {%0,%1,%2,%3}, [%4];"
    : "=r"(v.x),"=r"(v.y),"=r"(v.z),"=r"(v.w) : "l"(p));
  return v;
}
__device__ __forceinline__ void stcg16(void* p, unsigned short v){
  asm volatile("st.global.cg.u16 [%0], %1;" :: "l"(p), "h"(v) : "memory");
}
__device__ __forceinline__ unsigned h2pack(float a, float b){
  __half2 h = __floats2half2_rn(a, b);
  return *reinterpret_cast<unsigned*>(&h);
}
__device__ __forceinline__ void cpa16(void* sm, const void* g){
  unsigned s = (unsigned)__cvta_generic_to_shared(sm);
  asm volatile("cp.async.ca.shared.global [%0], [%1], 16;" :: "r"(s), "l"(g));
}
// fp16 frag-packed h: word index (u32 = half2) for element B[k=j][n=b].
__device__ __forceinline__ unsigned hW16(unsigned j, unsigned b){
  unsigned k16 = j>>4, kr = j&15u;
  unsigned ek = kr>>3, tig = (kr&7u)>>1;
  unsigned p = b>>4, col = b&15u, gid = col&7u, ecol = col>>3;
  return k16*512u + p*128u + (gid*4u+tig)*4u + ek + 2u*ecol;
}

// ---------------- phase 0: one-time fp16 conversion + init (R14-proven) ------
__global__ void convert_kernel(
    const float* __restrict__ x, const float* __restrict__ h0,
    const float* __restrict__ Wf, const float* __restrict__ Wi,
    const float* __restrict__ Wg, const float* __restrict__ Wo)
{
  const int idx = blockIdx.x*blockDim.x + threadIdx.x;
  const int stride = gridDim.x*blockDim.x;
  if (blockIdx.x==0) {
    if (threadIdx.x==0) g_bar = 0u;
    char* hbase = reinterpret_cast<char*>(g_h16[0]);
    for (int i = threadIdx.x; i < BATCH*HID; i += blockDim.x) {
      int b = i >> 10, j = i & 1023;
      unsigned byte = hW16((unsigned)j,(unsigned)b)*4u + (j&1u)*2u;
      __half hv = __float2half_rn(h0[i]);
      *reinterpret_cast<unsigned short*>(hbase + byte) =
          *reinterpret_cast<unsigned short*>(&hv);
    }
  }
  const int NX4 = (S_LEN*BATCH*HID)/4;
  unsigned* xh32 = reinterpret_cast<unsigned*>(g_xh);
  const float4* x4 = reinterpret_cast<const float4*>(x);
  for (int i = idx; i < NX4; i += stride){
    float4 v = x4[i];
    xh32[i*2]   = h2pack(v.x, v.y);
    xh32[i*2+1] = h2pack(v.z, v.w);
  }
  const int NW4 = (G4*HID)/4;
  unsigned* wh32 = reinterpret_cast<unsigned*>(g_wh);
  for (int i = idx; i < NW4; i += stride){
    int row = i >> 8;
    int c4  = (i & 255)*4;
    int gate = row >> 10, j = row & 1023;
    const float* Wp = (gate==0)?Wf:(gate==1)?Wi:(gate==2)?Wg:Wo;
    float4 v = *reinterpret_cast<const float4*>(&Wp[(size_t)j*2048 + c4]);
    wh32[i*2]   = h2pack(v.x, v.y);
    wh32[i*2+1] = h2pack(v.z, v.w);
  }
}

// ---------------- phase 1: xz = x @ Wx^T + b  (fp16 GEMM, 256x128 CTA tile) --
// 8 warps = 4 wm x 2 wn, warp tile 64x64 (acc[4][8][4] = 128 regs), 1 CTA/SM.
// Bigger warp tile cuts smem-crossbar bytes/MAC 1.5x -> MMA-issue-bound.
// cp.async double-buffered staging of pre-converted fp16 tiles.
// K-accumulation order per output element unchanged -> bit-identical results.
#define GSM_A0 0                      // A bufs: 256*40 halfs = 20480 B each
#define GSM_A1 20480
#define GSM_B0 40960                  // B bufs: 128*40 halfs = 10240 B each
#define GSM_B1 51200
#define GSMEM  61440
__global__ void __launch_bounds__(256,1) gemm_xz_kernel(
    const float* __restrict__ bfp, const float* __restrict__ bip,
    const float* __restrict__ bgp, const float* __restrict__ bop)
{
  extern __shared__ char gsm[];
  __half* as_[2] = { reinterpret_cast<__half*>(gsm + GSM_A0),
                     reinterpret_cast<__half*>(gsm + GSM_A1) };
  __half* bs_[2] = { reinterpret_cast<__half*>(gsm + GSM_B0),
                     reinterpret_cast<__half*>(gsm + GSM_B1) };

  const int m0 = blockIdx.y*256, n0 = blockIdx.x*128;
  const int tid = threadIdx.x, wid = tid>>5, lane = tid&31;
  const int wm = wid&3, wn = wid>>2, gid = lane>>2, tig = lane&3;
  const int gate = n0 >> 10;
  const float* bp = (gate==0)?bfp:(gate==1)?bip:(gate==2)?bgp:bop;

  float acc[4][8][4];
  #pragma unroll
  for (int u=0;u<4;u++)
    #pragma unroll
    for (int v=0;v<8;v++)
      #pragma unroll
      for (int w=0;w<4;w++) acc[u][v][w]=0.f;

  // copy K-block kb (32 halfs wide) into buffer buf.
  // A: 256 rows x 4 chunks = 1024; B: 128 rows x 4 = 512 chunks.
  auto issue_copy = [&](int buf, int kb){
    #pragma unroll
    for (int i=0;i<4;i++){
      int c = tid + i*256;
      int row = c>>2, ch = c&3;
      cpa16(&as_[buf][row*40 + ch*8], &g_xh[(size_t)(m0+row)*HID + kb + ch*8]);
    }
    #pragma unroll
    for (int i=0;i<2;i++){
      int c = tid + i*256;
      int row = c>>2, ch = c&3;
      cpa16(&bs_[buf][row*40 + ch*8], &g_wh[(size_t)(n0+row)*HID + kb + ch*8]);
    }
    asm volatile("cp.async.commit_group;");
  };

  issue_copy(0, 0);

  for (int it=0; it<32; it++) {
    if (it+1 < 32) issue_copy((it+1)&1, (it+1)*32);
    if (it+1 < 32) asm volatile("cp.async.wait_group 1;");
    else           asm volatile("cp.async.wait_group 0;");
    __syncthreads();

    const __half* as = as_[it&1];
    const __half* bs = bs_[it&1];
    #pragma unroll
    for (int k16=0;k16<2;k16++){
      const int kc = k16*16 + 2*tig;
      unsigned af[4][4], bfr[8][2];
      #pragma unroll
      for (int mt=0;mt<4;mt++){
        int row = wm*64 + mt*16;
        af[mt][0] = *reinterpret_cast<const unsigned*>(&as[(row+gid  )*40 + kc]);
        af[mt][1] = *reinterpret_cast<const unsigned*>(&as[(row+gid+8)*40 + kc]);
        af[mt][2] = *reinterpret_cast<const unsigned*>(&as[(row+gid  )*40 + kc + 8]);
        af[mt][3] = *reinterpret_cast<const unsigned*>(&as[(row+gid+8)*40 + kc + 8]);
      }
      #pragma unroll
      for (int nt=0;nt<8;nt++){
        int col = wn*64 + nt*8 + gid;
        bfr[nt][0] = *reinterpret_cast<const unsigned*>(&bs[col*40 + kc]);
        bfr[nt][1] = *reinterpret_cast<const unsigned*>(&bs[col*40 + kc + 8]);
      }
      #pragma unroll
      for (int mt=0;mt<4;mt++)
        #pragma unroll
        for (int nt=0;nt<8;nt++)
          mma16h(acc[mt][nt], af[mt], bfr[nt][0], bfr[nt][1]);
    }
    __syncthreads();
  }
  // epilogue: bias + [s][n][b] store
  #pragma unroll
  for (int mt=0;mt<4;mt++){
    #pragma unroll
    for (int nt=0;nt<8;nt++){
      int row0 = m0 + wm*64 + mt*16 + gid;
      int col  = n0 + wn*64 + nt*8 + tig*2;
      int j = col & 1023;
      float b0v = bp[j], b1v = bp[j+1];
      int s0 = row0>>6,     bb0 = row0&63;
      int s1 = (row0+8)>>6, bb1 = (row0+8)&63;
      size_t base0 = (size_t)s0*((size_t)G4*BATCH) + (size_t)col*BATCH;
      size_t base1 = (size_t)s1*((size_t)G4*BATCH) + (size_t)col*BATCH;
      g_xz[base0 + bb0]         = acc[mt][nt][0] + b0v;
      g_xz[base0 + BATCH + bb0] = acc[mt][nt][1] + b1v;
      g_xz[base1 + bb1]         = acc[mt][nt][2] + b0v;
      g_xz[base1 + BATCH + bb1] = acc[mt][nt][3] + b1v;
    }
  }
}

// ---------------- phase 2 smem layout (byte offsets) -------------------------
#define OFF_WHV   0          // 4096 uint4: fp16 A-frags (65536 B)
#define OFF_RED   65536      // 8 kw x (2 nh x 32 m x 32 b) f32, XOR-swizzled (65536 B)
#define OFF_ZBUF  131072     // 32 x 65 f32 (8320 B)
#define OFF_CS    139392     // 64 x 8 f32 (2048 B)
#define SMEM2_BYTES 141440

// ---------------- phase 2: persistent recurrent kernel (R13-proven, verbatim)
__global__ void __launch_bounds__(512,1) lstm_steps_kernel(
    const float* __restrict__ x, const float* __restrict__ c0,
    const float* __restrict__ Wf,const float* __restrict__ Wi,
    const float* __restrict__ Wg,const float* __restrict__ Wo,
    float* __restrict__ out)
{
  extern __shared__ char smem[];
  uint4*    whv4 = reinterpret_cast<uint4*>(smem + OFF_WHV);
  unsigned* whvw = reinterpret_cast<unsigned*>(smem + OFF_WHV);
  float*    red  = reinterpret_cast<float*>(smem + OFF_RED);
  float*    zbuf = reinterpret_cast<float*>(smem + OFF_ZBUF);   // stride 65
  float*    cs   = reinterpret_cast<float*>(smem + OFF_CS);

  const int tid = threadIdx.x, wid = tid>>5, lane = tid&31;
  const int gid = lane>>2, tig = lane&3;
  const int kw = wid & 7, nh = wid >> 3;
  const int cta = blockIdx.x, j0 = cta*8;

  for (int cc = 0; cc < 16; cc++){
    int c = cc*2 + (tid>>8);
    int gatec = c & 3, jl = c >> 2;
    const float* Wp = (gatec==0)?Wf:(gatec==1)?Wi:(gatec==2)?Wg:Wo;
    int kbase = (tid & 255)*4;
    float4 v = *reinterpret_cast<const float4*>(&Wp[(size_t)(j0+jl)*2048 + 1024 + kbase]);
    float vv[4] = {v.x, v.y, v.z, v.w};
    const int mt = c>>4, ihalf = (c>>3)&1, gidc = c&7;
    #pragma unroll
    for (int q2=0;q2<2;q2++){
      int k = kbase + q2*2;
      int k16 = k>>4, kr = k&15;
      int ek = kr>>3, tigk = (kr&7)>>1;
      unsigned word = (unsigned)(((k16*2 + mt)*128)
                    + (gidc*4 + tigk)*4 + ihalf + 2*ek);
      whvw[word] = h2pack(vv[q2*2], vv[q2*2+1]);
    }
  }
  {
    int b = tid>>3, jl = tid&7;
    cs[tid] = c0[b*HID + j0 + jl];
  }
  __syncthreads();

  const size_t HSEQ = (size_t)S_LEN*BATCH*HID;
  const int sm_m  = tid>>4;
  const int sm_nh = (tid>>3)&1;
  const int sm_bq = tid&7;
  const int sm_b  = sm_nh*32 + sm_bq*4;
  const int sm_gcol = (sm_m&3)*HID + j0 + (sm_m>>2);
  const int sm_rd = sm_nh*1024 + sm_m*32 + ((sm_bq ^ ((sm_m&3)<<1))<<2);
  const int gp_jl = tid & 7, gp_b = tid >> 3;
  const int gp_j  = j0 + gp_jl;
  const unsigned gp_hbyte = hW16((unsigned)gp_j,(unsigned)gp_b)*4u + ((unsigned)gp_j&1u)*2u;
  const unsigned bi0 = (unsigned)((nh*2  )*32 + lane);
  const unsigned bi1 = (unsigned)((nh*2+1)*32 + lane);

  float4 px = *reinterpret_cast<const float4*>(
      &g_xz[(size_t)sm_gcol*BATCH + sm_b]);
  float pxv = x[(size_t)gp_b*HID + gp_j];

  for (int s=0; s<S_LEN; s++){
    const uint4* hB = reinterpret_cast<const uint4*>(g_h16[s&1]);

    float acc[2][4][4];
    #pragma unroll
    for (int u=0;u<2;u++)
      #pragma unroll
      for (int v=0;v<4;v++)
        #pragma unroll
        for (int q=0;q<4;q++) acc[u][v][q]=0.f;

    uint4 bq[2][2];
    bq[0][0] = ldcg4(hB + ((unsigned)kw*128u + bi0));
    bq[0][1] = ldcg4(hB + ((unsigned)kw*128u + bi1));
    bq[1][0] = ldcg4(hB + ((unsigned)(kw+8)*128u + bi0));
    bq[1][1] = ldcg4(hB + ((unsigned)(kw+8)*128u + bi1));

    #pragma unroll
    for (int g=0; g<8; g++){
      const int k16 = kw + 8*g;
      uint4 c0v = bq[g&1][0], c1v = bq[g&1][1];
      if (g < 6){
        bq[g&1][0] = ldcg4(hB + ((unsigned)(k16+16)*128u + bi0));
        bq[g&1][1] = ldcg4(hB + ((unsigned)(k16+16)*128u + bi1));
      }
      uint4 av0 = whv4[(k16*2+0)*32 + lane];
      uint4 av1 = whv4[(k16*2+1)*32 + lane];
      mma16h(acc[0][0], reinterpret_cast<unsigned*>(&av0), c0v.x, c0v.y);
      mma16h(acc[0][1], reinterpret_cast<unsigned*>(&av0), c0v.z, c0v.w);
      mma16h(acc[0][2], reinterpret_cast<unsigned*>(&av0), c1v.x, c1v.y);
      mma16h(acc[0][3], reinterpret_cast<unsigned*>(&av0), c1v.z, c1v.w);
      mma16h(acc[1][0], reinterpret_cast<unsigned*>(&av1), c0v.x, c0v.y);
      mma16h(acc[1][1], reinterpret_cast<unsigned*>(&av1), c0v.z, c0v.w);
      mma16h(acc[1][2], reinterpret_cast<unsigned*>(&av1), c1v.x, c1v.y);
      mma16h(acc[1][3], reinterpret_cast<unsigned*>(&av1), c1v.z, c1v.w);
    }

    {
      float* rp = &red[kw*2048 + nh*1024];
      #pragma unroll
      for (int mt=0;mt<2;mt++){
        #pragma unroll
        for (int j=0;j<4;j++){
          int m  = mt*16 + gid;
          int bb = j*8 + 2*tig;
          int sw = (m&3)<<3;
          *reinterpret_cast<float2*>(&rp[m*32 + (bb ^ sw)])
              = make_float2(acc[mt][j][0], acc[mt][j][1]);
          *reinterpret_cast<float2*>(&rp[(m+8)*32 + (bb ^ sw)])
              = make_float2(acc[mt][j][2], acc[mt][j][3]);
        }
      }
    }
    __syncthreads();

    {
      float4 z = px;
      #pragma unroll
      for (int w8=0; w8<8; w8++){
        float4 a = *reinterpret_cast<const float4*>(&red[w8*2048 + sm_rd]);
        z.x += a.x; z.y += a.y; z.z += a.z; z.w += a.w;
      }
      zbuf[sm_m*65 + sm_b + 0] = z.x;
      zbuf[sm_m*65 + sm_b + 1] = z.y;
      zbuf[sm_m*65 + sm_b + 2] = z.z;
      zbuf[sm_m*65 + sm_b + 3] = z.w;
    }
    __syncthreads();

    if (s < S_LEN-1){
      px = *reinterpret_cast<const float4*>(
          &g_xz[(size_t)(s+1)*((size_t)G4*BATCH) + (size_t)sm_gcol*BATCH + sm_b]);
    }

    char* hwb = reinterpret_cast<char*>(g_h16[(s+1)&1]);
    float cc, hh;
    {
      int cbase = gp_jl*4;
      float zf = zbuf[(cbase+0)*65 + gp_b];
      float zi = zbuf[(cbase+1)*65 + gp_b];
      float zg = zbuf[(cbase+2)*65 + gp_b];
      float zo = zbuf[(cbase+3)*65 + gp_b];
      float fg = 0.5f*tanh_ap(0.5f*zf) + 0.5f;
      float ig = 0.5f*tanh_ap(0.5f*zi) + 0.5f;
      float gg = tanh_ap(zg);
      float og = 0.5f*tanh_ap(0.5f*zo) + 0.5f;
      cc = fg*cs[tid] + ig*gg;
      hh = og*tanh_ap(cc);
      cs[tid] = cc;
      __half hv = __float2half_rn(hh);
      stcg16(hwb + gp_hbyte, *reinterpret_cast<unsigned short*>(&hv));
    }

    if (s < S_LEN-1){
      __syncthreads();
      if (tid == 0){
        __threadfence();
        atomicAdd(&g_bar, 1u);
      }
    }

    {
      size_t xi = ((size_t)(s*BATCH + gp_b))*HID + gp_j;
      out[xi] = pxv + hh;
      if (s == S_LEN-1){
        out[HSEQ + (size_t)gp_b*HID + gp_j]                     = hh;  // h_f
        out[HSEQ + (size_t)BATCH*HID + (size_t)gp_b*HID + gp_j] = cc;  // c_f
      } else {
        pxv = x[xi + (size_t)BATCH*HID];
      }
    }

    if (s < S_LEN-1){
      if (tid == 0){
        unsigned target = (unsigned)RGRID * (unsigned)(s+1);
        while (ld_acq(&g_bar) < target) { }
      }
      __syncthreads();
    }
  }
}

// ---------------- launch ------------------------------------------------------
extern "C" void kernel_launch(void* const* d_in, const int* in_sizes, int n_in,
                              void* d_out, int out_size) {
  const float* x   = (const float*)d_in[0];
  const float* h0  = (const float*)d_in[1];
  const float* c0  = (const float*)d_in[2];
  const float* Wf  = (const float*)d_in[3];
  const float* bf_ = (const float*)d_in[4];
  const float* Wi  = (const float*)d_in[5];
  const float* bi_ = (const float*)d_in[6];
  const float* Wg  = (const float*)d_in[7];
  const float* bg_ = (const float*)d_in[8];
  const float* Wo  = (const float*)d_in[9];
  const float* bo_ = (const float*)d_in[10];
  float* out = (float*)d_out;

  cudaFuncSetAttribute(gemm_xz_kernel,
                       cudaFuncAttributeMaxDynamicSharedMemorySize, GSMEM);
  cudaFuncSetAttribute(lstm_steps_kernel,
                       cudaFuncAttributeMaxDynamicSharedMemorySize, SMEM2_BYTES);

  convert_kernel<<<1024,256>>>(x, h0, Wf,Wi,Wg,Wo);
  gemm_xz_kernel<<<dim3(32,64),256,GSMEM>>>(bf_,bi_,bg_,bo_);
  lstm_steps_kernel<<<RGRID,512,SMEM2_BYTES>>>(x, c0, Wf,Wi,Wg,Wo, out);
}

// round 17
// speedup vs baseline: 1.0786x; 1.0786x over previous
#include <cuda_runtime.h>
#include <cuda_fp16.h>
#include <cstdint>

#define S_LEN 256
#define BATCH 64
#define HID   1024
#define G4    4096
#define RGRID 128

// ---------------- device scratch (no runtime allocation allowed) ------------
__device__ float    g_xz[(size_t)S_LEN * G4 * BATCH];  // 256 MB, layout [s][n][b]
__device__ __half   g_xh[(size_t)S_LEN * BATCH * HID]; // x in fp16 (33.5 MB)
__device__ __half   g_wh[(size_t)G4 * HID];            // Wx fp16, row n = gate*1024+j (8 MB)
__device__ unsigned g_h16[2][HID*BATCH/2];             // h ping-pong, fp16 frag-packed
__device__ unsigned g_bar;                             // monotonic grid barrier

// ---------------- helpers ----------------------------------------------------
__device__ __forceinline__ float tanh_ap(float x){
  float y; asm("tanh.approx.f32 %0, %1;" : "=f"(y) : "f"(x)); return y;
}
__device__ __forceinline__ void mma16h(float* d, const unsigned* a, unsigned b0, unsigned b1){
  asm volatile("mma.sync.aligned.m16n8k16.row.col.f32.f16.f16.f32 "
      "{%0,%1,%2,%3},{%4,%5,%6,%7},{%8,%9},{%0,%1,%2,%3};"
      : "+f"(d[0]),"+f"(d[1]),"+f"(d[2]),"+f"(d[3])
      : "r"(a[0]),"r"(a[1]),"r"(a[2]),"r"(a[3]),"r"(b0),"r"(b1));
}
__device__ __forceinline__ unsigned ld_acq(const unsigned* p){
  unsigned v; asm volatile("ld.acquire.gpu.global.u32 %0, [%1];" : "=r"(v) : "l"(p)); return v;
}
__device__ __forceinline__ uint4 ldcg4(const uint4* p){
  uint4 v;
  asm volatile("ld.global.cg.v4.u32 {%0,%1,%2,%3}, [%4];"
    : "=r"(v.x),"=r"(v.y),"=r"(v.z),"=r"(v.w) : "l"(p));
  return v;
}
__device__ __forceinline__ void stcg16(void* p, unsigned short v){
  asm volatile("st.global.cg.u16 [%0], %1;" :: "l"(p), "h"(v) : "memory");
}
__device__ __forceinline__ unsigned h2pack(float a, float b){
  __half2 h = __floats2half2_rn(a, b);
  return *reinterpret_cast<unsigned*>(&h);
}
__device__ __forceinline__ void cpa16(void* sm, const void* g){
  unsigned s = (unsigned)__cvta_generic_to_shared(sm);
  asm volatile("cp.async.ca.shared.global [%0], [%1], 16;" :: "r"(s), "l"(g));
}
// fp16 frag-packed h: word index (u32 = half2) for element B[k=j][n=b].
__device__ __forceinline__ unsigned hW16(unsigned j, unsigned b){
  unsigned k16 = j>>4, kr = j&15u;
  unsigned ek = kr>>3, tig = (kr&7u)>>1;
  unsigned p = b>>4, col = b&15u, gid = col&7u, ecol = col>>3;
  return k16*512u + p*128u + (gid*4u+tig)*4u + ek + 2u*ecol;
}

// ---------------- phase 0: one-time fp16 conversion + init (R14-proven) ------
__global__ void convert_kernel(
    const float* __restrict__ x, const float* __restrict__ h0,
    const float* __restrict__ Wf, const float* __restrict__ Wi,
    const float* __restrict__ Wg, const float* __restrict__ Wo)
{
  const int idx = blockIdx.x*blockDim.x + threadIdx.x;
  const int stride = gridDim.x*blockDim.x;
  if (blockIdx.x==0) {
    if (threadIdx.x==0) g_bar = 0u;
    char* hbase = reinterpret_cast<char*>(g_h16[0]);
    for (int i = threadIdx.x; i < BATCH*HID; i += blockDim.x) {
      int b = i >> 10, j = i & 1023;
      unsigned byte = hW16((unsigned)j,(unsigned)b)*4u + (j&1u)*2u;
      __half hv = __float2half_rn(h0[i]);
      *reinterpret_cast<unsigned short*>(hbase + byte) =
          *reinterpret_cast<unsigned short*>(&hv);
    }
  }
  const int NX4 = (S_LEN*BATCH*HID)/4;
  unsigned* xh32 = reinterpret_cast<unsigned*>(g_xh);
  const float4* x4 = reinterpret_cast<const float4*>(x);
  for (int i = idx; i < NX4; i += stride){
    float4 v = x4[i];
    xh32[i*2]   = h2pack(v.x, v.y);
    xh32[i*2+1] = h2pack(v.z, v.w);
  }
  const int NW4 = (G4*HID)/4;
  unsigned* wh32 = reinterpret_cast<unsigned*>(g_wh);
  for (int i = idx; i < NW4; i += stride){
    int row = i >> 8;
    int c4  = (i & 255)*4;
    int gate = row >> 10, j = row & 1023;
    const float* Wp = (gate==0)?Wf:(gate==1)?Wi:(gate==2)?Wg:Wo;
    float4 v = *reinterpret_cast<const float4*>(&Wp[(size_t)j*2048 + c4]);
    wh32[i*2]   = h2pack(v.x, v.y);
    wh32[i*2+1] = h2pack(v.z, v.w);
  }
}

// ---------------- phase 1: xz = x @ Wx^T + b  (fp16 GEMM) --------------------
// CTA 128x128, 4 warps (2wm x 2wn), warp tile 64x64 (acc[4][8][4]), 2 CTAs/SM.
// Halves smem-crossbar bytes/MAC vs the 8-warp 32x64 layout while keeping the
// 2-CTA residency that hides sync/copy bubbles. cp.async double-buffered.
// K-accumulation order per output unchanged -> bit-identical results.
#define GSM_A0 0                      // A bufs: 128*40 halfs = 10240 B each
#define GSM_A1 10240
#define GSM_B0 20480                  // B bufs: 128*40 halfs = 10240 B each
#define GSM_B1 30720
#define GSMEM  40960
__global__ void __launch_bounds__(128,2) gemm_xz_kernel(
    const float* __restrict__ bfp, const float* __restrict__ bip,
    const float* __restrict__ bgp, const float* __restrict__ bop)
{
  extern __shared__ char gsm[];
  __half* as_[2] = { reinterpret_cast<__half*>(gsm + GSM_A0),
                     reinterpret_cast<__half*>(gsm + GSM_A1) };
  __half* bs_[2] = { reinterpret_cast<__half*>(gsm + GSM_B0),
                     reinterpret_cast<__half*>(gsm + GSM_B1) };

  const int m0 = blockIdx.y*128, n0 = blockIdx.x*128;
  const int tid = threadIdx.x, wid = tid>>5, lane = tid&31;
  const int wm = wid&1, wn = wid>>1, gid = lane>>2, tig = lane&3;
  const int gate = n0 >> 10;
  const float* bp = (gate==0)?bfp:(gate==1)?bip:(gate==2)?bgp:bop;

  float acc[4][8][4];
  #pragma unroll
  for (int u=0;u<4;u++)
    #pragma unroll
    for (int v=0;v<8;v++)
      #pragma unroll
      for (int w=0;w<4;w++) acc[u][v][w]=0.f;

  // copy K-block kb (32 halfs wide): A/B = 128 rows x 4 x 16B chunks = 512 each.
  auto issue_copy = [&](int buf, int kb){
    #pragma unroll
    for (int i=0;i<4;i++){
      int c = tid + i*128;
      int row = c>>2, ch = c&3;
      cpa16(&as_[buf][row*40 + ch*8], &g_xh[(size_t)(m0+row)*HID + kb + ch*8]);
    }
    #pragma unroll
    for (int i=0;i<4;i++){
      int c = tid + i*128;
      int row = c>>2, ch = c&3;
      cpa16(&bs_[buf][row*40 + ch*8], &g_wh[(size_t)(n0+row)*HID + kb + ch*8]);
    }
    asm volatile("cp.async.commit_group;");
  };

  issue_copy(0, 0);

  for (int it=0; it<32; it++) {
    if (it+1 < 32) issue_copy((it+1)&1, (it+1)*32);
    if (it+1 < 32) asm volatile("cp.async.wait_group 1;");
    else           asm volatile("cp.async.wait_group 0;");
    __syncthreads();

    const __half* as = as_[it&1];
    const __half* bs = bs_[it&1];
    #pragma unroll
    for (int k16=0;k16<2;k16++){
      const int kc = k16*16 + 2*tig;
      unsigned af[4][4], bfr[8][2];
      #pragma unroll
      for (int mt=0;mt<4;mt++){
        int row = wm*64 + mt*16;
        af[mt][0] = *reinterpret_cast<const unsigned*>(&as[(row+gid  )*40 + kc]);
        af[mt][1] = *reinterpret_cast<const unsigned*>(&as[(row+gid+8)*40 + kc]);
        af[mt][2] = *reinterpret_cast<const unsigned*>(&as[(row+gid  )*40 + kc + 8]);
        af[mt][3] = *reinterpret_cast<const unsigned*>(&as[(row+gid+8)*40 + kc + 8]);
      }
      #pragma unroll
      for (int nt=0;nt<8;nt++){
        int col = wn*64 + nt*8 + gid;
        bfr[nt][0] = *reinterpret_cast<const unsigned*>(&bs[col*40 + kc]);
        bfr[nt][1] = *reinterpret_cast<const unsigned*>(&bs[col*40 + kc + 8]);
      }
      #pragma unroll
      for (int mt=0;mt<4;mt++)
        #pragma unroll
        for (int nt=0;nt<8;nt++)
          mma16h(acc[mt][nt], af[mt], bfr[nt][0], bfr[nt][1]);
    }
    __syncthreads();
  }
  // epilogue: bias + [s][n][b] store
  #pragma unroll
  for (int mt=0;mt<4;mt++){
    #pragma unroll
    for (int nt=0;nt<8;nt++){
      int row0 = m0 + wm*64 + mt*16 + gid;
      int col  = n0 + wn*64 + nt*8 + tig*2;
      int j = col & 1023;
      float b0v = bp[j], b1v = bp[j+1];
      int s0 = row0>>6,     bb0 = row0&63;
      int s1 = (row0+8)>>6, bb1 = (row0+8)&63;
      size_t base0 = (size_t)s0*((size_t)G4*BATCH) + (size_t)col*BATCH;
      size_t base1 = (size_t)s1*((size_t)G4*BATCH) + (size_t)col*BATCH;
      g_xz[base0 + bb0]         = acc[mt][nt][0] + b0v;
      g_xz[base0 + BATCH + bb0] = acc[mt][nt][1] + b1v;
      g_xz[base1 + bb1]         = acc[mt][nt][2] + b0v;
      g_xz[base1 + BATCH + bb1] = acc[mt][nt][3] + b1v;
    }
  }
}

// ---------------- phase 2 smem layout (byte offsets) -------------------------
#define OFF_WHV   0          // 4096 uint4: fp16 A-frags (65536 B)
#define OFF_RED   65536      // 8 kw x (2 nh x 32 m x 32 b) f32, XOR-swizzled (65536 B)
#define OFF_ZBUF  131072     // 32 x 65 f32 (8320 B)
#define OFF_CS    139392     // 64 x 8 f32 (2048 B)
#define SMEM2_BYTES 141440

// ---------------- phase 2: persistent recurrent kernel (R13-proven, verbatim)
__global__ void __launch_bounds__(512,1) lstm_steps_kernel(
    const float* __restrict__ x, const float* __restrict__ c0,
    const float* __restrict__ Wf,const float* __restrict__ Wi,
    const float* __restrict__ Wg,const float* __restrict__ Wo,
    float* __restrict__ out)
{
  extern __shared__ char smem[];
  uint4*    whv4 = reinterpret_cast<uint4*>(smem + OFF_WHV);
  unsigned* whvw = reinterpret_cast<unsigned*>(smem + OFF_WHV);
  float*    red  = reinterpret_cast<float*>(smem + OFF_RED);
  float*    zbuf = reinterpret_cast<float*>(smem + OFF_ZBUF);   // stride 65
  float*    cs   = reinterpret_cast<float*>(smem + OFF_CS);

  const int tid = threadIdx.x, wid = tid>>5, lane = tid&31;
  const int gid = lane>>2, tig = lane&3;
  const int kw = wid & 7, nh = wid >> 3;
  const int cta = blockIdx.x, j0 = cta*8;

  for (int cc = 0; cc < 16; cc++){
    int c = cc*2 + (tid>>8);
    int gatec = c & 3, jl = c >> 2;
    const float* Wp = (gatec==0)?Wf:(gatec==1)?Wi:(gatec==2)?Wg:Wo;
    int kbase = (tid & 255)*4;
    float4 v = *reinterpret_cast<const float4*>(&Wp[(size_t)(j0+jl)*2048 + 1024 + kbase]);
    float vv[4] = {v.x, v.y, v.z, v.w};
    const int mt = c>>4, ihalf = (c>>3)&1, gidc = c&7;
    #pragma unroll
    for (int q2=0;q2<2;q2++){
      int k = kbase + q2*2;
      int k16 = k>>4, kr = k&15;
      int ek = kr>>3, tigk = (kr&7)>>1;
      unsigned word = (unsigned)(((k16*2 + mt)*128)
                    + (gidc*4 + tigk)*4 + ihalf + 2*ek);
      whvw[word] = h2pack(vv[q2*2], vv[q2*2+1]);
    }
  }
  {
    int b = tid>>3, jl = tid&7;
    cs[tid] = c0[b*HID + j0 + jl];
  }
  __syncthreads();

  const size_t HSEQ = (size_t)S_LEN*BATCH*HID;
  const int sm_m  = tid>>4;
  const int sm_nh = (tid>>3)&1;
  const int sm_bq = tid&7;
  const int sm_b  = sm_nh*32 + sm_bq*4;
  const int sm_gcol = (sm_m&3)*HID + j0 + (sm_m>>2);
  const int sm_rd = sm_nh*1024 + sm_m*32 + ((sm_bq ^ ((sm_m&3)<<1))<<2);
  const int gp_jl = tid & 7, gp_b = tid >> 3;
  const int gp_j  = j0 + gp_jl;
  const unsigned gp_hbyte = hW16((unsigned)gp_j,(unsigned)gp_b)*4u + ((unsigned)gp_j&1u)*2u;
  const unsigned bi0 = (unsigned)((nh*2  )*32 + lane);
  const unsigned bi1 = (unsigned)((nh*2+1)*32 + lane);

  float4 px = *reinterpret_cast<const float4*>(
      &g_xz[(size_t)sm_gcol*BATCH + sm_b]);
  float pxv = x[(size_t)gp_b*HID + gp_j];

  for (int s=0; s<S_LEN; s++){
    const uint4* hB = reinterpret_cast<const uint4*>(g_h16[s&1]);

    float acc[2][4][4];
    #pragma unroll
    for (int u=0;u<2;u++)
      #pragma unroll
      for (int v=0;v<4;v++)
        #pragma unroll
        for (int q=0;q<4;q++) acc[u][v][q]=0.f;

    uint4 bq[2][2];
    bq[0][0] = ldcg4(hB + ((unsigned)kw*128u + bi0));
    bq[0][1] = ldcg4(hB + ((unsigned)kw*128u + bi1));
    bq[1][0] = ldcg4(hB + ((unsigned)(kw+8)*128u + bi0));
    bq[1][1] = ldcg4(hB + ((unsigned)(kw+8)*128u + bi1));

    #pragma unroll
    for (int g=0; g<8; g++){
      const int k16 = kw + 8*g;
      uint4 c0v = bq[g&1][0], c1v = bq[g&1][1];
      if (g < 6){
        bq[g&1][0] = ldcg4(hB + ((unsigned)(k16+16)*128u + bi0));
        bq[g&1][1] = ldcg4(hB + ((unsigned)(k16+16)*128u + bi1));
      }
      uint4 av0 = whv4[(k16*2+0)*32 + lane];
      uint4 av1 = whv4[(k16*2+1)*32 + lane];
      mma16h(acc[0][0], reinterpret_cast<unsigned*>(&av0), c0v.x, c0v.y);
      mma16h(acc[0][1], reinterpret_cast<unsigned*>(&av0), c0v.z, c0v.w);
      mma16h(acc[0][2], reinterpret_cast<unsigned*>(&av0), c1v.x, c1v.y);
      mma16h(acc[0][3], reinterpret_cast<unsigned*>(&av0), c1v.z, c1v.w);
      mma16h(acc[1][0], reinterpret_cast<unsigned*>(&av1), c0v.x, c0v.y);
      mma16h(acc[1][1], reinterpret_cast<unsigned*>(&av1), c0v.z, c0v.w);
      mma16h(acc[1][2], reinterpret_cast<unsigned*>(&av1), c1v.x, c1v.y);
      mma16h(acc[1][3], reinterpret_cast<unsigned*>(&av1), c1v.z, c1v.w);
    }

    {
      float* rp = &red[kw*2048 + nh*1024];
      #pragma unroll
      for (int mt=0;mt<2;mt++){
        #pragma unroll
        for (int j=0;j<4;j++){
          int m  = mt*16 + gid;
          int bb = j*8 + 2*tig;
          int sw = (m&3)<<3;
          *reinterpret_cast<float2*>(&rp[m*32 + (bb ^ sw)])
              = make_float2(acc[mt][j][0], acc[mt][j][1]);
          *reinterpret_cast<float2*>(&rp[(m+8)*32 + (bb ^ sw)])
              = make_float2(acc[mt][j][2], acc[mt][j][3]);
        }
      }
    }
    __syncthreads();

    {
      float4 z = px;
      #pragma unroll
      for (int w8=0; w8<8; w8++){
        float4 a = *reinterpret_cast<const float4*>(&red[w8*2048 + sm_rd]);
        z.x += a.x; z.y += a.y; z.z += a.z; z.w += a.w;
      }
      zbuf[sm_m*65 + sm_b + 0] = z.x;
      zbuf[sm_m*65 + sm_b + 1] = z.y;
      zbuf[sm_m*65 + sm_b + 2] = z.z;
      zbuf[sm_m*65 + sm_b + 3] = z.w;
    }
    __syncthreads();

    if (s < S_LEN-1){
      px = *reinterpret_cast<const float4*>(
          &g_xz[(size_t)(s+1)*((size_t)G4*BATCH) + (size_t)sm_gcol*BATCH + sm_b]);
    }

    char* hwb = reinterpret_cast<char*>(g_h16[(s+1)&1]);
    float cc, hh;
    {
      int cbase = gp_jl*4;
      float zf = zbuf[(cbase+0)*65 + gp_b];
      float zi = zbuf[(cbase+1)*65 + gp_b];
      float zg = zbuf[(cbase+2)*65 + gp_b];
      float zo = zbuf[(cbase+3)*65 + gp_b];
      float fg = 0.5f*tanh_ap(0.5f*zf) + 0.5f;
      float ig = 0.5f*tanh_ap(0.5f*zi) + 0.5f;
      float gg = tanh_ap(zg);
      float og = 0.5f*tanh_ap(0.5f*zo) + 0.5f;
      cc = fg*cs[tid] + ig*gg;
      hh = og*tanh_ap(cc);
      cs[tid] = cc;
      __half hv = __float2half_rn(hh);
      stcg16(hwb + gp_hbyte, *reinterpret_cast<unsigned short*>(&hv));
    }

    if (s < S_LEN-1){
      __syncthreads();
      if (tid == 0){
        __threadfence();
        atomicAdd(&g_bar, 1u);
      }
    }

    {
      size_t xi = ((size_t)(s*BATCH + gp_b))*HID + gp_j;
      out[xi] = pxv + hh;
      if (s == S_LEN-1){
        out[HSEQ + (size_t)gp_b*HID + gp_j]                     = hh;  // h_f
        out[HSEQ + (size_t)BATCH*HID + (size_t)gp_b*HID + gp_j] = cc;  // c_f
      } else {
        pxv = x[xi + (size_t)BATCH*HID];
      }
    }

    if (s < S_LEN-1){
      if (tid == 0){
        unsigned target = (unsigned)RGRID * (unsigned)(s+1);
        while (ld_acq(&g_bar) < target) { }
      }
      __syncthreads();
    }
  }
}

// ---------------- launch ------------------------------------------------------
extern "C" void kernel_launch(void* const* d_in, const int* in_sizes, int n_in,
                              void* d_out, int out_size) {
  const float* x   = (const float*)d_in[0];
  const float* h0  = (const float*)d_in[1];
  const float* c0  = (const float*)d_in[2];
  const float* Wf  = (const float*)d_in[3];
  const float* bf_ = (const float*)d_in[4];
  const float* Wi  = (const float*)d_in[5];
  const float* bi_ = (const float*)d_in[6];
  const float* Wg  = (const float*)d_in[7];
  const float* bg_ = (const float*)d_in[8];
  const float* Wo  = (const float*)d_in[9];
  const float* bo_ = (const float*)d_in[10];
  float* out = (float*)d_out;

  cudaFuncSetAttribute(gemm_xz_kernel,
                       cudaFuncAttributeMaxDynamicSharedMemorySize, GSMEM);
  cudaFuncSetAttribute(lstm_steps_kernel,
                       cudaFuncAttributeMaxDynamicSharedMemorySize, SMEM2_BYTES);

  convert_kernel<<<1024,256>>>(x, h0, Wf,Wi,Wg,Wo);
  gemm_xz_kernel<<<dim3(32,128),128,GSMEM>>>(bf_,bi_,bg_,bo_);
  lstm_steps_kernel<<<RGRID,512,SMEM2_BYTES>>>(x, c0, Wf,Wi,Wg,Wo, out);
}